// round 8
// baseline (speedup 1.0000x reference)
#include <cuda_runtime.h>
#include <math.h>

#define BB 16
#define NN 2048
#define MM 32
#define PP 48
#define TT 5
#define CC (PP*TT)   // 240

#define WPB 8        // warps (=atoms) per block
#define TH1 (WPB*32) // 256

// Per-atom BN partials: g_part[atom] = {sum, sumsq} over 240 channels.
// Unconditionally overwritten every launch -> deterministic, no zeroing.
__device__ float2 g_part[BB * NN];

__device__ __forceinline__ float ex2_fast(float x) {
    float r; asm("ex2.approx.f32 %0, %1;" : "=f"(r) : "f"(x)); return r;
}
__device__ __forceinline__ float sqrt_fast(float x) {
    float r; asm("sqrt.approx.f32 %0, %1;" : "=f"(r) : "f"(x)); return r;
}

// ---------------------------------------------------------------------------
// Kernel 1: warp-per-atom radial symmetry functions + BN partials.
// No shared memory, no __syncthreads.
//  Gather:  lane = neighbor m. R + type computed per lane.
//  Compute: lane = radial index; slot0 p=lane, slot1 p=lane+32 (lane<16).
//           For each type k: ballot mask of neighbors with t==k, walk set
//           bits with __ffs, broadcast R via __shfl. Accumulators are
//           scalars (type index is compile-time) -> no routing instructions.
//  Output:  op[k*48 + p] coalesced; warp-reduced (s,s2) -> g_part[atom].
// ---------------------------------------------------------------------------
__global__ __launch_bounds__(TH1)
void rsf_kernel(const float* __restrict__ X,
                const float* __restrict__ rc,
                const float* __restrict__ rs,
                const float* __restrict__ re,
                const int*   __restrict__ Nbrs,
                const int*   __restrict__ NbrsZ,
                float*       __restrict__ out)
{
    const int lane = threadIdx.x & 31;
    const int warp = threadIdx.x >> 5;
    const int atom = blockIdx.x * WPB + warp;   // atom = b*N + n
    const int b    = atom >> 11;

    // own coordinates (uniform across warp)
    const float x0 = __ldg(X + atom * 3 + 0);
    const float x1 = __ldg(X + atom * 3 + 1);
    const float x2 = __ldg(X + atom * 3 + 2);

    // gather: lane = neighbor m
    const int nb = __ldg(Nbrs  + atom * MM + lane);
    const int z  = __ldg(NbrsZ + atom * MM + lane);
    const float* np_ = X + ((b << 11) + nb) * 3;
    const float dx = __ldg(np_ + 0) - x0;
    const float dy = __ldg(np_ + 1) - x1;
    const float dz = __ldg(np_ + 2) - x2;
    const float Rl = sqrt_fast(dx*dx + dy*dy + dz*dz);

    int t = -1;
    if      (z == 1)  t = 0;
    else if (z == 6)  t = 1;
    else if (z == 7)  t = 2;
    else if (z == 8)  t = 3;
    else if (z == 16) t = 4;

    // per-lane radial params: slot0 j0=lane, slot1 j1=lane+32 (lane<16)
    const int j0 = lane;
    const int j1 = (lane < 16) ? (lane + 32) : lane;   // clamp (results unused)
    const float rc0 = __ldg(rc + j0), rs0 = __ldg(rs + j0);
    const float rc1 = __ldg(rc + j1), rs1 = __ldg(rs + j1);
    const float ne0 = -__ldg(re + j0) * 1.44269504088896f;
    const float ne1 = -__ldg(re + j1) * 1.44269504088896f;
    const float pc0 = 3.14159265358979f / rc0;
    const float pc1 = 3.14159265358979f / rc1;

    float s = 0.0f, s2 = 0.0f;
    float* op = out + (size_t)atom * CC;

    #pragma unroll
    for (int k = 0; k < TT; k++) {
        unsigned mask = __ballot_sync(0xffffffffu, t == k);
        float a0 = 0.0f, a1 = 0.0f;
        while (mask) {
            const int i = __ffs(mask) - 1;
            mask &= mask - 1;
            const float R = __shfl_sync(0xffffffffu, Rl, i);
            // slot 0
            const float d0 = R - rs0;
            const float e0 = ex2_fast(ne0 * d0 * d0);
            float f0 = fmaf(__cosf(R * pc0), 0.5f, 0.5f);
            f0 = (R <= rc0) ? f0 : 0.0f;
            a0 = fmaf(e0, f0, a0);
            // slot 1
            const float d1 = R - rs1;
            const float e1 = ex2_fast(ne1 * d1 * d1);
            float f1 = fmaf(__cosf(R * pc1), 0.5f, 0.5f);
            f1 = (R <= rc1) ? f1 : 0.0f;
            a1 = fmaf(e1, f1, a1);
        }
        op[k * PP + lane] = a0;
        if (lane < 16) {
            op[k * PP + 32 + lane] = a1;
            s += a1; s2 = fmaf(a1, a1, s2);
        }
        s += a0; s2 = fmaf(a0, a0, s2);
    }

    // warp reduce (s,s2) -> per-atom BN partial
    #pragma unroll
    for (int o = 16; o > 0; o >>= 1) {
        s  += __shfl_down_sync(0xffffffffu, s,  o);
        s2 += __shfl_down_sync(0xffffffffu, s2, o);
    }
    if (lane == 0) g_part[atom] = make_float2(s, s2);
}

// ---------------------------------------------------------------------------
// Kernel 2: BatchNorm normalize (unchanged from R7; measured 12.1us).
// One block per n; warp 0 reduces 16 per-atom partials -> mean/inv;
// tid<240 handles float4 column c4=tid%60 for 4 rows b=(tid/60)*4+r.
// ---------------------------------------------------------------------------
__global__ __launch_bounds__(256)
void norm_kernel(float4* __restrict__ out4)
{
    const int n   = blockIdx.x;
    const int tid = threadIdx.x;

    __shared__ float sMean, sInv;

    if (tid < 32) {
        float s = 0.0f, s2 = 0.0f;
        if (tid < BB) {
            const float2 p = g_part[tid * NN + n];
            s = p.x; s2 = p.y;
        }
        #pragma unroll
        for (int o = 8; o > 0; o >>= 1) {
            s  += __shfl_down_sync(0xffffffffu, s,  o);
            s2 += __shfl_down_sync(0xffffffffu, s2, o);
        }
        if (tid == 0) {
            const float invn = 1.0f / (float)(BB * CC);
            const float mean = s * invn;
            float var = s2 * invn - mean * mean;
            var = fmaxf(var, 0.0f);
            sMean = mean;
            sInv  = rsqrtf(var + 1e-5f);
        }
    }
    __syncthreads();

    if (tid < 240) {
        const float mean = sMean;
        const float inv  = sInv;
        const int bq = tid / 60;              // 0..3
        const int c4 = tid % 60;              // float4 index within row

        float4 v[4];
        size_t idx[4];
        #pragma unroll
        for (int r = 0; r < 4; r++) {
            const int b = bq * 4 + r;
            idx[r] = (size_t)(b * NN + n) * (CC / 4) + c4;
            v[r] = out4[idx[r]];
        }
        #pragma unroll
        for (int r = 0; r < 4; r++) {
            v[r].x = (v[r].x - mean) * inv;
            v[r].y = (v[r].y - mean) * inv;
            v[r].z = (v[r].z - mean) * inv;
            v[r].w = (v[r].w - mean) * inv;
            out4[idx[r]] = v[r];
        }
    }
}

// ---------------------------------------------------------------------------
extern "C" void kernel_launch(void* const* d_in, const int* in_sizes, int n_in,
                              void* d_out, int out_size)
{
    const float* X     = (const float*)d_in[0];
    const float* rc    = (const float*)d_in[1];
    const float* rs    = (const float*)d_in[2];
    const float* re    = (const float*)d_in[3];
    const int*   Nbrs  = (const int*)  d_in[4];
    const int*   NbrsZ = (const int*)  d_in[5];

    const int nAtoms = BB * NN;                 // 32768
    rsf_kernel<<<nAtoms / WPB, TH1>>>(X, rc, rs, re, Nbrs, NbrsZ, (float*)d_out);
    norm_kernel<<<NN, 256>>>((float4*)d_out);
}

// round 9
// speedup vs baseline: 1.0552x; 1.0552x over previous
#include <cuda_runtime.h>
#include <math.h>

#define BB 16
#define NN 2048
#define MM 32
#define PP 48
#define TT 5
#define CC (PP*TT)   // 240

#define APB 8            // atoms per block
#define TH1 (APB*PP)     // 384 threads = 12 warps; phase A uses warps 0..7

// Per-atom BN partials: g_part[atom] = {sum, sumsq} over 240 channels.
// Unconditionally overwritten every launch -> deterministic, no zeroing.
__device__ float2 g_part[BB * NN];

__device__ __forceinline__ float ex2_fast(float x) {
    float r; asm("ex2.approx.f32 %0, %1;" : "=f"(r) : "f"(x)); return r;
}
__device__ __forceinline__ float sqrt_fast(float x) {
    float r; asm("sqrt.approx.f32 %0, %1;" : "=f"(r) : "f"(x)); return r;
}

// ---------------------------------------------------------------------------
// Kernel 1: radial symmetry functions + BN partials (R6 structure, verbatim;
// grid split in two so ncu -s 5 lands on this kernel instead of norm).
// Phase A (warps 0..7): warp w = atom, lane = neighbor. Compute R, map Z to
//   type bin; single-ballot compaction of VALID neighbors into sRT[w][].
// Phase B (all 384 threads): thread -> (atom g, radial j). One uniform loop
//   over valid neighbors; predicated adds route to type accumulators.
// Phase C (warps 0..7): per-atom reduce of per-thread (s,s2) -> g_part.
// ---------------------------------------------------------------------------
__global__ __launch_bounds__(TH1)
void rsf_kernel(const float* __restrict__ X,
                const float* __restrict__ rc,
                const float* __restrict__ rs,
                const float* __restrict__ re,
                const int*   __restrict__ Nbrs,
                const int*   __restrict__ NbrsZ,
                float*       __restrict__ out,
                int blockOffset)
{
    __shared__ float2 sRT[APB][MM];
    __shared__ int    sCnt[APB];
    __shared__ float2 sPart[TH1];

    const int tid  = threadIdx.x;
    const int warp = tid >> 5;
    const int lane = tid & 31;
    const int baseAtom = (blockOffset + blockIdx.x) * APB;   // atom = b*N + n

    // ---------------- Phase A ----------------
    if (warp < APB) {
        const int atom = baseAtom + warp;
        const int b    = atom >> 11;
        const float* xp = X + atom * 3;
        const float x0 = xp[0], x1 = xp[1], x2 = xp[2];

        const int nb = Nbrs [atom * MM + lane];
        const int z  = NbrsZ[atom * MM + lane];
        const float* np_ = X + ((b << 11) + nb) * 3;
        const float dx = np_[0] - x0;
        const float dy = np_[1] - x1;
        const float dz = np_[2] - x2;
        const float R  = sqrt_fast(dx*dx + dy*dy + dz*dz);

        int t = -1;
        if      (z == 1)  t = 0;
        else if (z == 6)  t = 1;
        else if (z == 7)  t = 2;
        else if (z == 8)  t = 3;
        else if (z == 16) t = 4;

        const unsigned mask = __ballot_sync(0xffffffffu, t >= 0);
        if (t >= 0) {
            const int pos = __popc(mask & ((1u << lane) - 1u));
            sRT[warp][pos] = make_float2(R, __int_as_float(t));
        }
        if (lane == 0) sCnt[warp] = __popc(mask);
    }
    __syncthreads();

    // ---------------- Phase B ----------------
    const int g = tid / PP;        // atom within block
    const int j = tid % PP;        // radial index p
    const int atom = baseAtom + g;

    const float myrc  = rc[j];
    const float myrs  = rs[j];
    const float nre2  = -re[j] * 1.44269504088896f;  // fold log2(e)
    const float pi_rc = 3.14159265358979f / myrc;
    const float2* rt  = sRT[g];
    const int total   = sCnt[g];

    float acc[TT];
    #pragma unroll
    for (int tt = 0; tt < TT; tt++) acc[tt] = 0.0f;

    int m = 0;
    for (; m + 2 <= total; m += 2) {
        const float2 a0 = rt[m];
        const float2 a1 = rt[m + 1];
        const float R0 = a0.x, R1 = a1.x;
        const int   t0 = __float_as_int(a0.y);
        const int   t1 = __float_as_int(a1.y);
        const float d0 = R0 - myrs;
        const float d1 = R1 - myrs;
        const float e0 = ex2_fast(nre2 * d0 * d0);
        const float e1 = ex2_fast(nre2 * d1 * d1);
        const float c0 = __cosf(R0 * pi_rc);
        const float c1 = __cosf(R1 * pi_rc);
        float f0 = fmaf(c0, 0.5f, 0.5f);
        float f1 = fmaf(c1, 0.5f, 0.5f);
        f0 = (R0 <= myrc) ? f0 : 0.0f;
        f1 = (R1 <= myrc) ? f1 : 0.0f;
        const float v0 = e0 * f0;
        const float v1 = e1 * f1;
        #pragma unroll
        for (int tt = 0; tt < TT; tt++) {
            if (t0 == tt) acc[tt] += v0;
            if (t1 == tt) acc[tt] += v1;
        }
    }
    if (m < total) {
        const float2 a0 = rt[m];
        const float R0 = a0.x;
        const int   t0 = __float_as_int(a0.y);
        const float d0 = R0 - myrs;
        const float e0 = ex2_fast(nre2 * d0 * d0);
        const float c0 = __cosf(R0 * pi_rc);
        float f0 = fmaf(c0, 0.5f, 0.5f);
        f0 = (R0 <= myrc) ? f0 : 0.0f;
        const float v0 = e0 * f0;
        #pragma unroll
        for (int tt = 0; tt < TT; tt++) {
            if (t0 == tt) acc[tt] += v0;
        }
    }

    float s = 0.0f, s2 = 0.0f;
    {
        float* op = out + (size_t)atom * CC;
        #pragma unroll
        for (int tt = 0; tt < TT; tt++) {
            const float a = acc[tt];
            op[tt * PP + j] = a;
            s  += a;
            s2 = fmaf(a, a, s2);
        }
    }
    sPart[tid] = make_float2(s, s2);
    __syncthreads();

    // ---------------- Phase C: per-atom reduce of (s,s2) ----------------
    if (warp < APB) {
        const float2 p0 = sPart[warp * PP + lane];
        float s  = p0.x;
        float s2 = p0.y;
        if (lane < PP - 32) {
            const float2 p1 = sPart[warp * PP + 32 + lane];
            s  += p1.x;
            s2 += p1.y;
        }
        #pragma unroll
        for (int o = 16; o > 0; o >>= 1) {
            s  += __shfl_down_sync(0xffffffffu, s,  o);
            s2 += __shfl_down_sync(0xffffffffu, s2, o);
        }
        if (lane == 0) g_part[baseAtom + warp] = make_float2(s, s2);
    }
}

// ---------------------------------------------------------------------------
// Kernel 2: BatchNorm normalize (R7 float4 version; grid split in two).
// One block per n; warp 0 reduces 16 per-atom partials -> mean/inv;
// tid<240 handles float4 column c4=tid%60 for 4 rows b=(tid/60)*4+r.
// ---------------------------------------------------------------------------
__global__ __launch_bounds__(256)
void norm_kernel(float4* __restrict__ out4, int nOffset)
{
    const int n   = nOffset + blockIdx.x;
    const int tid = threadIdx.x;

    __shared__ float sMean, sInv;

    if (tid < 32) {
        float s = 0.0f, s2 = 0.0f;
        if (tid < BB) {
            const float2 p = g_part[tid * NN + n];
            s = p.x; s2 = p.y;
        }
        #pragma unroll
        for (int o = 8; o > 0; o >>= 1) {
            s  += __shfl_down_sync(0xffffffffu, s,  o);
            s2 += __shfl_down_sync(0xffffffffu, s2, o);
        }
        if (tid == 0) {
            const float invn = 1.0f / (float)(BB * CC);
            const float mean = s * invn;
            float var = s2 * invn - mean * mean;
            var = fmaxf(var, 0.0f);
            sMean = mean;
            sInv  = rsqrtf(var + 1e-5f);
        }
    }
    __syncthreads();

    if (tid < 240) {
        const float mean = sMean;
        const float inv  = sInv;
        const int bq = tid / 60;              // 0..3
        const int c4 = tid % 60;              // float4 index within row

        float4 v[4];
        size_t idx[4];
        #pragma unroll
        for (int r = 0; r < 4; r++) {
            const int b = bq * 4 + r;
            idx[r] = (size_t)(b * NN + n) * (CC / 4) + c4;
            v[r] = out4[idx[r]];
        }
        #pragma unroll
        for (int r = 0; r < 4; r++) {
            v[r].x = (v[r].x - mean) * inv;
            v[r].y = (v[r].y - mean) * inv;
            v[r].z = (v[r].z - mean) * inv;
            v[r].w = (v[r].w - mean) * inv;
            out4[idx[r]] = v[r];
        }
    }
}

// ---------------------------------------------------------------------------
extern "C" void kernel_launch(void* const* d_in, const int* in_sizes, int n_in,
                              void* d_out, int out_size)
{
    const float* X     = (const float*)d_in[0];
    const float* rc    = (const float*)d_in[1];
    const float* rs    = (const float*)d_in[2];
    const float* re    = (const float*)d_in[3];
    const int*   Nbrs  = (const int*)  d_in[4];
    const int*   NbrsZ = (const int*)  d_in[5];
    float* out = (float*)d_out;

    const int nAtoms  = BB * NN;                 // 32768
    const int nBlocks = nAtoms / APB;            // 4096
    const int half    = nBlocks / 2;

    // 4 launches per call -> ncu (-s 5) profiles launch index 5 mod 4 = 1,
    // i.e. the second rsf launch, finally giving visibility into rsf.
    rsf_kernel<<<half, TH1>>>(X, rc, rs, re, Nbrs, NbrsZ, out, 0);
    rsf_kernel<<<half, TH1>>>(X, rc, rs, re, Nbrs, NbrsZ, out, half);
    norm_kernel<<<NN / 2, 256>>>((float4*)out, 0);
    norm_kernel<<<NN / 2, 256>>>((float4*)out, NN / 2);
}

// round 10
// speedup vs baseline: 1.1692x; 1.1080x over previous
#include <cuda_runtime.h>
#include <math.h>

#define BB 16
#define NN 2048
#define MM 32
#define PP 48
#define TT 5
#define CC (PP*TT)   // 240

#define APB 8            // atoms per block
#define TH1 (APB*PP)     // 384 threads = 12 warps; phase A uses warps 0..7

// Per-atom BN partials: g_part[atom] = {sum, sumsq} over 240 channels.
// Unconditionally overwritten every launch -> deterministic, no zeroing.
__device__ float2 g_part[BB * NN];

__device__ __forceinline__ float ex2_fast(float x) {
    float r; asm("ex2.approx.f32 %0, %1;" : "=f"(r) : "f"(x)); return r;
}
__device__ __forceinline__ float sqrt_fast(float x) {
    float r; asm("sqrt.approx.f32 %0, %1;" : "=f"(r) : "f"(x)); return r;
}

// ---------------------------------------------------------------------------
// Kernel 1: radial symmetry functions + BN partials (R6 structure, verbatim —
// best measured rsf at 21.5us).
// Phase A (warps 0..7): warp w = atom, lane = neighbor. Compute R, map Z to
//   type bin; single-ballot compaction of VALID neighbors into sRT[w][].
// Phase B (all 384 threads): thread -> (atom g, radial j). One uniform loop
//   over valid neighbors; predicated adds route to type accumulators.
// Phase C (warps 0..7): per-atom reduce of per-thread (s,s2) -> g_part.
// ---------------------------------------------------------------------------
__global__ __launch_bounds__(TH1)
void rsf_kernel(const float* __restrict__ X,
                const float* __restrict__ rc,
                const float* __restrict__ rs,
                const float* __restrict__ re,
                const int*   __restrict__ Nbrs,
                const int*   __restrict__ NbrsZ,
                float*       __restrict__ out)
{
    __shared__ float2 sRT[APB][MM];
    __shared__ int    sCnt[APB];
    __shared__ float2 sPart[TH1];

    const int tid  = threadIdx.x;
    const int warp = tid >> 5;
    const int lane = tid & 31;
    const int baseAtom = blockIdx.x * APB;      // atom = b*N + n

    // ---------------- Phase A ----------------
    if (warp < APB) {
        const int atom = baseAtom + warp;
        const int b    = atom >> 11;
        const float* xp = X + atom * 3;
        const float x0 = xp[0], x1 = xp[1], x2 = xp[2];

        const int nb = Nbrs [atom * MM + lane];
        const int z  = NbrsZ[atom * MM + lane];
        const float* np_ = X + ((b << 11) + nb) * 3;
        const float dx = np_[0] - x0;
        const float dy = np_[1] - x1;
        const float dz = np_[2] - x2;
        const float R  = sqrt_fast(dx*dx + dy*dy + dz*dz);

        int t = -1;
        if      (z == 1)  t = 0;
        else if (z == 6)  t = 1;
        else if (z == 7)  t = 2;
        else if (z == 8)  t = 3;
        else if (z == 16) t = 4;

        const unsigned mask = __ballot_sync(0xffffffffu, t >= 0);
        if (t >= 0) {
            const int pos = __popc(mask & ((1u << lane) - 1u));
            sRT[warp][pos] = make_float2(R, __int_as_float(t));
        }
        if (lane == 0) sCnt[warp] = __popc(mask);
    }
    __syncthreads();

    // ---------------- Phase B ----------------
    const int g = tid / PP;        // atom within block
    const int j = tid % PP;        // radial index p
    const int atom = baseAtom + g;

    const float myrc  = rc[j];
    const float myrs  = rs[j];
    const float nre2  = -re[j] * 1.44269504088896f;  // fold log2(e)
    const float pi_rc = 3.14159265358979f / myrc;
    const float2* rt  = sRT[g];
    const int total   = sCnt[g];

    float acc[TT];
    #pragma unroll
    for (int tt = 0; tt < TT; tt++) acc[tt] = 0.0f;

    int m = 0;
    for (; m + 2 <= total; m += 2) {
        const float2 a0 = rt[m];
        const float2 a1 = rt[m + 1];
        const float R0 = a0.x, R1 = a1.x;
        const int   t0 = __float_as_int(a0.y);
        const int   t1 = __float_as_int(a1.y);
        const float d0 = R0 - myrs;
        const float d1 = R1 - myrs;
        const float e0 = ex2_fast(nre2 * d0 * d0);
        const float e1 = ex2_fast(nre2 * d1 * d1);
        const float c0 = __cosf(R0 * pi_rc);
        const float c1 = __cosf(R1 * pi_rc);
        float f0 = fmaf(c0, 0.5f, 0.5f);
        float f1 = fmaf(c1, 0.5f, 0.5f);
        f0 = (R0 <= myrc) ? f0 : 0.0f;
        f1 = (R1 <= myrc) ? f1 : 0.0f;
        const float v0 = e0 * f0;
        const float v1 = e1 * f1;
        #pragma unroll
        for (int tt = 0; tt < TT; tt++) {
            if (t0 == tt) acc[tt] += v0;
            if (t1 == tt) acc[tt] += v1;
        }
    }
    if (m < total) {
        const float2 a0 = rt[m];
        const float R0 = a0.x;
        const int   t0 = __float_as_int(a0.y);
        const float d0 = R0 - myrs;
        const float e0 = ex2_fast(nre2 * d0 * d0);
        const float c0 = __cosf(R0 * pi_rc);
        float f0 = fmaf(c0, 0.5f, 0.5f);
        f0 = (R0 <= myrc) ? f0 : 0.0f;
        const float v0 = e0 * f0;
        #pragma unroll
        for (int tt = 0; tt < TT; tt++) {
            if (t0 == tt) acc[tt] += v0;
        }
    }

    float s = 0.0f, s2 = 0.0f;
    {
        float* op = out + (size_t)atom * CC;
        #pragma unroll
        for (int tt = 0; tt < TT; tt++) {
            const float a = acc[tt];
            op[tt * PP + j] = a;
            s  += a;
            s2 = fmaf(a, a, s2);
        }
    }
    sPart[tid] = make_float2(s, s2);
    __syncthreads();

    // ---------------- Phase C: per-atom reduce of (s,s2) ----------------
    if (warp < APB) {
        const float2 p0 = sPart[warp * PP + lane];
        float s  = p0.x;
        float s2 = p0.y;
        if (lane < PP - 32) {
            const float2 p1 = sPart[warp * PP + 32 + lane];
            s  += p1.x;
            s2 += p1.y;
        }
        #pragma unroll
        for (int o = 16; o > 0; o >>= 1) {
            s  += __shfl_down_sync(0xffffffffu, s,  o);
            s2 += __shfl_down_sync(0xffffffffu, s2, o);
        }
        if (lane == 0) g_part[baseAtom + warp] = make_float2(s, s2);
    }
}

// ---------------------------------------------------------------------------
// Kernel 2: BatchNorm normalize (R7 float4 version, verbatim — best measured
// norm at 12.1us). One block per n; warp 0 reduces 16 per-atom partials ->
// mean/inv; tid<240 handles float4 column c4=tid%60 for rows b=(tid/60)*4+r.
// ---------------------------------------------------------------------------
__global__ __launch_bounds__(256)
void norm_kernel(float4* __restrict__ out4)
{
    const int n   = blockIdx.x;
    const int tid = threadIdx.x;

    __shared__ float sMean, sInv;

    if (tid < 32) {
        float s = 0.0f, s2 = 0.0f;
        if (tid < BB) {
            const float2 p = g_part[tid * NN + n];
            s = p.x; s2 = p.y;
        }
        #pragma unroll
        for (int o = 8; o > 0; o >>= 1) {
            s  += __shfl_down_sync(0xffffffffu, s,  o);
            s2 += __shfl_down_sync(0xffffffffu, s2, o);
        }
        if (tid == 0) {
            const float invn = 1.0f / (float)(BB * CC);
            const float mean = s * invn;
            float var = s2 * invn - mean * mean;
            var = fmaxf(var, 0.0f);
            sMean = mean;
            sInv  = rsqrtf(var + 1e-5f);
        }
    }
    __syncthreads();

    if (tid < 240) {
        const float mean = sMean;
        const float inv  = sInv;
        const int bq = tid / 60;              // 0..3
        const int c4 = tid % 60;              // float4 index within row

        float4 v[4];
        size_t idx[4];
        #pragma unroll
        for (int r = 0; r < 4; r++) {
            const int b = bq * 4 + r;
            idx[r] = (size_t)(b * NN + n) * (CC / 4) + c4;
            v[r] = out4[idx[r]];
        }
        #pragma unroll
        for (int r = 0; r < 4; r++) {
            v[r].x = (v[r].x - mean) * inv;
            v[r].y = (v[r].y - mean) * inv;
            v[r].z = (v[r].z - mean) * inv;
            v[r].w = (v[r].w - mean) * inv;
            out4[idx[r]] = v[r];
        }
    }
}

// ---------------------------------------------------------------------------
extern "C" void kernel_launch(void* const* d_in, const int* in_sizes, int n_in,
                              void* d_out, int out_size)
{
    const float* X     = (const float*)d_in[0];
    const float* rc    = (const float*)d_in[1];
    const float* rs    = (const float*)d_in[2];
    const float* re    = (const float*)d_in[3];
    const int*   Nbrs  = (const int*)  d_in[4];
    const int*   NbrsZ = (const int*)  d_in[5];

    const int nAtoms = BB * NN;                 // 32768
    rsf_kernel<<<nAtoms / APB, TH1>>>(X, rc, rs, re, Nbrs, NbrsZ, (float*)d_out);
    norm_kernel<<<NN, 256>>>((float4*)d_out);
}